// round 11
// baseline (speedup 1.0000x reference)
#include <cuda_runtime.h>
#include <math.h>

#define B_  16
#define N_  577
#define D_  1024
#define E_  8
#define R_  16
#define C3_ 3072
#define NPAD 640
#define NCH 16
#define KQ  2

#define WU_SIZE   (B_ * N_ * C3_)
#define RL_OFF    (WU_SIZE)
#define TI_OFF    (RL_OFF + B_ * E_)
#define EW_OFF    (TI_OFF + B_ * 2)
#define IMP_OFF   (EW_OFF + B_ * E_)
#define LOAD_OFF  (IMP_OFF + E_)

__device__ float g_part[NCH][B_][D_];
__device__ int   g_sel[B_][2];
__device__ float g_coef[B_][2];
__device__ float g_w[B_][2];
__device__ float g_Ut[KQ][B_][32][NPAD];  // k-split partials of U^T

__device__ __forceinline__ void ffma2_acc(float2& d, float2 a, float2 b) {
    asm("fma.rn.f32x2 %0, %1, %2, %0;"
        : "+l"(reinterpret_cast<unsigned long long&>(d))
        : "l"(reinterpret_cast<unsigned long long&>(a)),
          "l"(reinterpret_cast<unsigned long long&>(b)));
}

// ---- Kernel 1: pooled partial sums over 16 n-chunks ----
__global__ __launch_bounds__(256) void prep_kernel(const float* __restrict__ tokens) {
    int bx = blockIdx.x;
    int b = bx >> 4, ch = bx & 15;
    int tid = threadIdx.x;
    int n0 = ch * 37, n1 = min(N_, n0 + 37);

    float4 acc = make_float4(0.f, 0.f, 0.f, 0.f);
    const float* base = tokens + (size_t)b * N_ * D_;
    for (int n = n0; n < n1; n++) {
        float4 v = *(const float4*)&base[n * D_ + tid * 4];
        acc.x += v.x; acc.y += v.y; acc.z += v.z; acc.w += v.w;
    }
    *(float4*)&g_part[ch][b][tid * 4] = acc;
}

// ---- Kernel 2: per-batch logits + top-2 softmax + aux outputs ----
__global__ __launch_bounds__(256) void logits_topk(const float* __restrict__ gate_w,
                                                   const float* __restrict__ scaling,
                                                   float* __restrict__ out) {
    __shared__ float pooled_s[D_];
    __shared__ float logits_s[E_];
    __shared__ int   m_s[2];
    __shared__ float w_s[2];

    const int b = blockIdx.x;
    const int tid = threadIdx.x;
    const int wid = tid >> 5, lane = tid & 31;

    float4 a = make_float4(0.f, 0.f, 0.f, 0.f);
    #pragma unroll
    for (int ch = 0; ch < NCH; ch++) {
        float4 v = *(const float4*)&g_part[ch][b][tid * 4];
        a.x += v.x; a.y += v.y; a.z += v.z; a.w += v.w;
    }
    *(float4*)&pooled_s[tid * 4] = a;
    __syncthreads();

    {
        float acc = 0.f;
        for (int d = lane; d < D_; d += 32)
            acc += pooled_s[d] * gate_w[d * E_ + wid];
        #pragma unroll
        for (int o = 16; o; o >>= 1) acc += __shfl_down_sync(0xffffffffu, acc, o);
        if (lane == 0) {
            float lg = acc * (1.0f / (float)N_);
            logits_s[wid] = lg;
            out[RL_OFF + b * E_ + wid] = lg;
        }
    }
    __syncthreads();

    if (tid == 0) {
        float v[E_];
        #pragma unroll
        for (int e = 0; e < E_; e++) v[e] = logits_s[e];
        int m1 = 0;
        #pragma unroll
        for (int e = 1; e < E_; e++) if (v[e] > v[m1]) m1 = e;
        int m2 = (m1 == 0) ? 1 : 0;
        #pragma unroll
        for (int e = 0; e < E_; e++) if (e != m1 && v[e] > v[m2]) m2 = e;

        float e2 = expf(v[m2] - v[m1]);
        float inv = 1.0f / (1.0f + e2);
        float w1 = inv, w2 = e2 * inv;

        m_s[0] = m1; m_s[1] = m2;
        w_s[0] = w1; w_s[1] = w2;
        g_sel[b][0] = m1; g_sel[b][1] = m2;
        g_w[b][0] = w1; g_w[b][1] = w2;
        g_coef[b][0] = w1 * scaling[m1];
        g_coef[b][1] = w2 * scaling[m2];
        out[TI_OFF + b * 2 + 0] = (float)m1;
        out[TI_OFF + b * 2 + 1] = (float)m2;
    }
    __syncthreads();

    if (tid < E_) {
        float w = (tid == m_s[0]) ? w_s[0] : ((tid == m_s[1]) ? w_s[1] : 0.f);
        out[EW_OFF + b * E_ + tid] = w;
    }
}

// ---- Kernel 3: U partials, smem-transposed coalesced stores (proven) ----
#define UKC 64
__global__ __launch_bounds__(256) void u_kernel(const float* __restrict__ tokens,
                                                const float* __restrict__ lora_a,
                                                float* __restrict__ out) {
    __shared__ union {
        struct { float T[32][UKC + 4]; float A[32][UKC + 4]; } p;
        float red[4][32][36];
    } sm;

    const int n0 = blockIdx.x * 32;
    const int b  = blockIdx.y;
    const int kq = blockIdx.z;
    const int tid = threadIdx.x;

    if (blockIdx.x == 0 && blockIdx.y == 0 && blockIdx.z == 0 && tid < E_) {
        float imp = 0.f; int ld = 0;
        for (int bb = 0; bb < B_; bb++) {
            if (g_sel[bb][0] == tid) { imp += g_w[bb][0]; ld++; }
            if (g_sel[bb][1] == tid) { imp += g_w[bb][1]; ld++; }
        }
        out[IMP_OFF + tid] = imp;
        out[LOAD_OFF + tid] = (float)ld;
    }

    const int s0 = g_sel[b][0], s1 = g_sel[b][1];
    const float c0f = g_coef[b][0], c1f = g_coef[b][1];

    const int kg   = tid >> 5;
    const int rowg = (tid >> 3) & 3;
    const int colg = tid & 7;

    float2 acc[8][4];
    #pragma unroll
    for (int i = 0; i < 8; i++)
        #pragma unroll
        for (int j = 0; j < 4; j++) acc[i][j] = make_float2(0.f, 0.f);

    const int kend = kq * 512 + 512;
    for (int k0 = kq * 512; k0 < kend; k0 += UKC) {
        #pragma unroll
        for (int t = 0; t < 2; t++) {
            int idx = tid + t * 256;
            int r = idx >> 4;
            int q = (idx & 15) * 4;
            float4 tv = make_float4(0.f, 0.f, 0.f, 0.f);
            if (n0 + r < N_)
                tv = *(const float4*)&tokens[((size_t)b * N_ + n0 + r) * D_ + k0 + q];
            *(float4*)&sm.p.T[r][q] = tv;

            int e = (r < 16) ? s0 : s1;
            float cf = (r < 16) ? c0f : c1f;
            float4 av = *(const float4*)&lora_a[((size_t)e * R_ + (r & 15)) * D_ + k0 + q];
            av.x *= cf; av.y *= cf; av.z *= cf; av.w *= cf;
            *(float4*)&sm.p.A[r][q] = av;
        }
        __syncthreads();

        const int kb = kg * 8;
        #pragma unroll
        for (int ks = 0; ks < 8; ks += 4) {
            float4 avv[4];
            #pragma unroll
            for (int j = 0; j < 4; j++)
                avv[j] = *(const float4*)&sm.p.A[colg + 8 * j][kb + ks];
            #pragma unroll
            for (int i = 0; i < 8; i++) {
                float4 tv = *(const float4*)&sm.p.T[rowg + 4 * i][kb + ks];
                #pragma unroll
                for (int j = 0; j < 4; j++) {
                    ffma2_acc(acc[i][j], make_float2(tv.x, tv.y),
                                         make_float2(avv[j].x, avv[j].y));
                    ffma2_acc(acc[i][j], make_float2(tv.z, tv.w),
                                         make_float2(avv[j].z, avv[j].w));
                }
            }
        }
        __syncthreads();
    }

    float v[8][4];
    #pragma unroll
    for (int i = 0; i < 8; i++)
        #pragma unroll
        for (int j = 0; j < 4; j++) v[i][j] = acc[i][j].x + acc[i][j].y;

    for (int off = 4; off; off >>= 1) {
        if (kg >= off && kg < 2 * off) {
            #pragma unroll
            for (int i = 0; i < 8; i++)
                #pragma unroll
                for (int j = 0; j < 4; j++)
                    sm.red[kg - off][colg + 8 * j][rowg + 4 * i] = v[i][j];
        }
        __syncthreads();
        if (kg < off) {
            #pragma unroll
            for (int i = 0; i < 8; i++)
                #pragma unroll
                for (int j = 0; j < 4; j++)
                    v[i][j] += sm.red[kg][colg + 8 * j][rowg + 4 * i];
        }
        __syncthreads();
    }

    if (kg == 0) {
        #pragma unroll
        for (int i = 0; i < 8; i++)
            #pragma unroll
            for (int j = 0; j < 4; j++)
                sm.red[0][colg + 8 * j][rowg + 4 * i] = v[i][j];
    }
    __syncthreads();
    {
        int j  = tid >> 3;
        int nq = (tid & 7) * 4;
        *(float4*)&g_Ut[kq][b][j][n0 + nq] = *(const float4*)&sm.red[0][j][nq];
    }
}

// ---- Kernel 4: out[64n x 256c], two c-half passes (32 acc regs), 3 blk/SM ----
__global__ __launch_bounds__(256, 3) void out_kernel(const float* __restrict__ lora_b,
                                                     float* __restrict__ out) {
    __shared__ float Bsm[32][260];
    __shared__ float Usm[32][68];

    const int c0 = blockIdx.x * 256;
    const int n0 = blockIdx.y * 64;
    const int b  = blockIdx.z;
    const int tid = threadIdx.x;
    const int s0 = g_sel[b][0], s1 = g_sel[b][1];

    #pragma unroll
    for (int t = 0; t < 2; t++) {
        int idx = tid + t * 256;
        int k = idx >> 4;
        int nq = (idx & 15) * 4;
        float4 s = *(const float4*)&g_Ut[0][b][k][n0 + nq];
        float4 p = *(const float4*)&g_Ut[1][b][k][n0 + nq];
        s.x += p.x; s.y += p.y; s.z += p.z; s.w += p.w;
        *(float4*)&Usm[k][nq] = s;
    }
    #pragma unroll
    for (int t = 0; t < 8; t++) {
        int idx = tid + t * 256;
        int c  = idx & 255;
        int er = idx >> 8;
        int e  = (er >> 2) ? s1 : s0;
        int rq = er & 3;
        float4 v = *(const float4*)&lora_b[((size_t)e * C3_ + c0 + c) * R_ + rq * 4];
        int kb = (er >> 2) * 16 + rq * 4;
        Bsm[kb + 0][c] = v.x;
        Bsm[kb + 1][c] = v.y;
        Bsm[kb + 2][c] = v.z;
        Bsm[kb + 3][c] = v.w;
    }
    __syncthreads();

    const int rowg = tid >> 5;
    const int cg4  = (tid & 31) * 4;

    #pragma unroll
    for (int half = 0; half < 2; half++) {
        const int ch = half * 128;
        float2 acc[8][2];
        #pragma unroll
        for (int i = 0; i < 8; i++) {
            acc[i][0] = make_float2(0.f, 0.f);
            acc[i][1] = make_float2(0.f, 0.f);
        }

        #pragma unroll
        for (int k = 0; k < 32; k++) {
            float4 u0 = *(const float4*)&Usm[k][rowg * 4];
            float4 u1 = *(const float4*)&Usm[k][32 + rowg * 4];
            float4 bv = *(const float4*)&Bsm[k][ch + cg4];
            float2 bp0 = make_float2(bv.x, bv.y);
            float2 bp1 = make_float2(bv.z, bv.w);
            float us[8] = {u0.x, u0.y, u0.z, u0.w, u1.x, u1.y, u1.z, u1.w};
            #pragma unroll
            for (int i = 0; i < 8; i++) {
                float2 ud = make_float2(us[i], us[i]);
                ffma2_acc(acc[i][0], ud, bp0);
                ffma2_acc(acc[i][1], ud, bp1);
            }
        }

        #pragma unroll
        for (int i = 0; i < 8; i++) {
            int n = n0 + ((i < 4) ? (rowg * 4 + i) : (32 + rowg * 4 + i - 4));
            if (n < N_) {
                float* orow = &out[((size_t)b * N_ + n) * C3_ + c0 + ch];
                *(float4*)&orow[cg4] =
                    make_float4(acc[i][0].x, acc[i][0].y, acc[i][1].x, acc[i][1].y);
            }
        }
    }
}

// ---------------------------------------------------------------------------
extern "C" void kernel_launch(void* const* d_in, const int* in_sizes, int n_in,
                              void* d_out, int out_size) {
    const float* tokens  = (const float*)d_in[0];
    const float* gate_w  = (const float*)d_in[1];
    const float* lora_a  = (const float*)d_in[2];
    const float* lora_b  = (const float*)d_in[3];
    const float* scaling = (const float*)d_in[4];
    float* out = (float*)d_out;

    prep_kernel<<<256, 256>>>(tokens);
    logits_topk<<<B_, 256>>>(gate_w, scaling, out);
    u_kernel<<<dim3(19, B_, KQ), 256>>>(tokens, lora_a, out);
    out_kernel<<<dim3(12, 10, B_), 256>>>(lora_b, out);
}

// round 12
// speedup vs baseline: 3.1757x; 3.1757x over previous
#include <cuda_runtime.h>
#include <math.h>

#define B_  16
#define N_  577
#define D_  1024
#define E_  8
#define R_  16
#define C3_ 3072
#define NPAD 640
#define NCH 16
#define KQ  2

#define WU_SIZE   (B_ * N_ * C3_)
#define RL_OFF    (WU_SIZE)
#define TI_OFF    (RL_OFF + B_ * E_)
#define EW_OFF    (TI_OFF + B_ * 2)
#define IMP_OFF   (EW_OFF + B_ * E_)
#define LOAD_OFF  (IMP_OFF + E_)

__device__ float g_part[NCH][B_][D_];
__device__ int   g_sel[B_][2];
__device__ float g_coef[B_][2];
__device__ float g_w[B_][2];
__device__ float g_Ut[KQ][B_][32][NPAD];  // k-split partials of U^T

__device__ __forceinline__ void ffma2_acc(float2& d, float2 a, float2 b) {
    asm("fma.rn.f32x2 %0, %1, %2, %0;"
        : "+l"(reinterpret_cast<unsigned long long&>(d))
        : "l"(reinterpret_cast<unsigned long long&>(a)),
          "l"(reinterpret_cast<unsigned long long&>(b)));
}

// ---- Kernel 1: pooled partial sums over 16 n-chunks ----
__global__ __launch_bounds__(256) void prep_kernel(const float* __restrict__ tokens) {
    int bx = blockIdx.x;
    int b = bx >> 4, ch = bx & 15;
    int tid = threadIdx.x;
    int n0 = ch * 37, n1 = min(N_, n0 + 37);

    float4 acc = make_float4(0.f, 0.f, 0.f, 0.f);
    const float* base = tokens + (size_t)b * N_ * D_;
    for (int n = n0; n < n1; n++) {
        float4 v = *(const float4*)&base[n * D_ + tid * 4];
        acc.x += v.x; acc.y += v.y; acc.z += v.z; acc.w += v.w;
    }
    *(float4*)&g_part[ch][b][tid * 4] = acc;
}

// ---- Kernel 2: per-batch logits + top-2 softmax + aux outputs ----
__global__ __launch_bounds__(256) void logits_topk(const float* __restrict__ gate_w,
                                                   const float* __restrict__ scaling,
                                                   float* __restrict__ out) {
    __shared__ float pooled_s[D_];
    __shared__ float logits_s[E_];
    __shared__ int   m_s[2];
    __shared__ float w_s[2];

    const int b = blockIdx.x;
    const int tid = threadIdx.x;
    const int wid = tid >> 5, lane = tid & 31;

    float4 a = make_float4(0.f, 0.f, 0.f, 0.f);
    #pragma unroll
    for (int ch = 0; ch < NCH; ch++) {
        float4 v = *(const float4*)&g_part[ch][b][tid * 4];
        a.x += v.x; a.y += v.y; a.z += v.z; a.w += v.w;
    }
    *(float4*)&pooled_s[tid * 4] = a;
    __syncthreads();

    {
        float acc = 0.f;
        for (int d = lane; d < D_; d += 32)
            acc += pooled_s[d] * gate_w[d * E_ + wid];
        #pragma unroll
        for (int o = 16; o; o >>= 1) acc += __shfl_down_sync(0xffffffffu, acc, o);
        if (lane == 0) {
            float lg = acc * (1.0f / (float)N_);
            logits_s[wid] = lg;
            out[RL_OFF + b * E_ + wid] = lg;
        }
    }
    __syncthreads();

    if (tid == 0) {
        float v[E_];
        #pragma unroll
        for (int e = 0; e < E_; e++) v[e] = logits_s[e];
        int m1 = 0;
        #pragma unroll
        for (int e = 1; e < E_; e++) if (v[e] > v[m1]) m1 = e;
        int m2 = (m1 == 0) ? 1 : 0;
        #pragma unroll
        for (int e = 0; e < E_; e++) if (e != m1 && v[e] > v[m2]) m2 = e;

        float e2 = expf(v[m2] - v[m1]);
        float inv = 1.0f / (1.0f + e2);
        float w1 = inv, w2 = e2 * inv;

        m_s[0] = m1; m_s[1] = m2;
        w_s[0] = w1; w_s[1] = w2;
        g_sel[b][0] = m1; g_sel[b][1] = m2;
        g_w[b][0] = w1; g_w[b][1] = w2;
        g_coef[b][0] = w1 * scaling[m1];
        g_coef[b][1] = w2 * scaling[m2];
        out[TI_OFF + b * 2 + 0] = (float)m1;
        out[TI_OFF + b * 2 + 1] = (float)m2;
    }
    __syncthreads();

    if (tid < E_) {
        float w = (tid == m_s[0]) ? w_s[0] : ((tid == m_s[1]) ? w_s[1] : 0.f);
        out[EW_OFF + b * E_ + tid] = w;
    }
}

// ---- Kernel 3: U partials, smem-transposed coalesced stores (proven) ----
#define UKC 64
__global__ __launch_bounds__(256) void u_kernel(const float* __restrict__ tokens,
                                                const float* __restrict__ lora_a,
                                                float* __restrict__ out) {
    __shared__ union {
        struct { float T[32][UKC + 4]; float A[32][UKC + 4]; } p;
        float red[4][32][36];
    } sm;

    const int n0 = blockIdx.x * 32;
    const int b  = blockIdx.y;
    const int kq = blockIdx.z;
    const int tid = threadIdx.x;

    if (blockIdx.x == 0 && blockIdx.y == 0 && blockIdx.z == 0 && tid < E_) {
        float imp = 0.f; int ld = 0;
        for (int bb = 0; bb < B_; bb++) {
            if (g_sel[bb][0] == tid) { imp += g_w[bb][0]; ld++; }
            if (g_sel[bb][1] == tid) { imp += g_w[bb][1]; ld++; }
        }
        out[IMP_OFF + tid] = imp;
        out[LOAD_OFF + tid] = (float)ld;
    }

    const int s0 = g_sel[b][0], s1 = g_sel[b][1];
    const float c0f = g_coef[b][0], c1f = g_coef[b][1];

    const int kg   = tid >> 5;
    const int rowg = (tid >> 3) & 3;
    const int colg = tid & 7;

    float2 acc[8][4];
    #pragma unroll
    for (int i = 0; i < 8; i++)
        #pragma unroll
        for (int j = 0; j < 4; j++) acc[i][j] = make_float2(0.f, 0.f);

    const int kend = kq * 512 + 512;
    for (int k0 = kq * 512; k0 < kend; k0 += UKC) {
        #pragma unroll
        for (int t = 0; t < 2; t++) {
            int idx = tid + t * 256;
            int r = idx >> 4;
            int q = (idx & 15) * 4;
            float4 tv = make_float4(0.f, 0.f, 0.f, 0.f);
            if (n0 + r < N_)
                tv = *(const float4*)&tokens[((size_t)b * N_ + n0 + r) * D_ + k0 + q];
            *(float4*)&sm.p.T[r][q] = tv;

            int e = (r < 16) ? s0 : s1;
            float cf = (r < 16) ? c0f : c1f;
            float4 av = *(const float4*)&lora_a[((size_t)e * R_ + (r & 15)) * D_ + k0 + q];
            av.x *= cf; av.y *= cf; av.z *= cf; av.w *= cf;
            *(float4*)&sm.p.A[r][q] = av;
        }
        __syncthreads();

        const int kb = kg * 8;
        #pragma unroll
        for (int ks = 0; ks < 8; ks += 4) {
            float4 avv[4];
            #pragma unroll
            for (int j = 0; j < 4; j++)
                avv[j] = *(const float4*)&sm.p.A[colg + 8 * j][kb + ks];
            #pragma unroll
            for (int i = 0; i < 8; i++) {
                float4 tv = *(const float4*)&sm.p.T[rowg + 4 * i][kb + ks];
                #pragma unroll
                for (int j = 0; j < 4; j++) {
                    ffma2_acc(acc[i][j], make_float2(tv.x, tv.y),
                                         make_float2(avv[j].x, avv[j].y));
                    ffma2_acc(acc[i][j], make_float2(tv.z, tv.w),
                                         make_float2(avv[j].z, avv[j].w));
                }
            }
        }
        __syncthreads();
    }

    float v[8][4];
    #pragma unroll
    for (int i = 0; i < 8; i++)
        #pragma unroll
        for (int j = 0; j < 4; j++) v[i][j] = acc[i][j].x + acc[i][j].y;

    for (int off = 4; off; off >>= 1) {
        if (kg >= off && kg < 2 * off) {
            #pragma unroll
            for (int i = 0; i < 8; i++)
                #pragma unroll
                for (int j = 0; j < 4; j++)
                    sm.red[kg - off][colg + 8 * j][rowg + 4 * i] = v[i][j];
        }
        __syncthreads();
        if (kg < off) {
            #pragma unroll
            for (int i = 0; i < 8; i++)
                #pragma unroll
                for (int j = 0; j < 4; j++)
                    v[i][j] += sm.red[kg][colg + 8 * j][rowg + 4 * i];
        }
        __syncthreads();
    }

    if (kg == 0) {
        #pragma unroll
        for (int i = 0; i < 8; i++)
            #pragma unroll
            for (int j = 0; j < 4; j++)
                sm.red[0][colg + 8 * j][rowg + 4 * i] = v[i][j];
    }
    __syncthreads();
    {
        int j  = tid >> 3;
        int nq = (tid & 7) * 4;
        *(float4*)&g_Ut[kq][b][j][n0 + nq] = *(const float4*)&sm.red[0][j][nq];
    }
}

// ---- Kernel 4: out, B tile loaded ONCE per block, 2 n-tiles per block ----
// grid (12 c-tiles, 5 n-pairs, 16 b); NO reg cap (proven (256,2) inner loop)
__global__ __launch_bounds__(256, 2) void out_kernel(const float* __restrict__ lora_b,
                                                     float* __restrict__ out) {
    __shared__ float Bsm[32][260];
    __shared__ float Usm[32][68];

    const int c0 = blockIdx.x * 256;
    const int b  = blockIdx.z;
    const int tid = threadIdx.x;
    const int s0 = g_sel[b][0], s1 = g_sel[b][1];

    // B tile: load once for both n-tiles
    #pragma unroll
    for (int t = 0; t < 8; t++) {
        int idx = tid + t * 256;
        int c  = idx & 255;
        int er = idx >> 8;
        int e  = (er >> 2) ? s1 : s0;
        int rq = er & 3;
        float4 v = *(const float4*)&lora_b[((size_t)e * C3_ + c0 + c) * R_ + rq * 4];
        int kb = (er >> 2) * 16 + rq * 4;
        Bsm[kb + 0][c] = v.x;
        Bsm[kb + 1][c] = v.y;
        Bsm[kb + 2][c] = v.z;
        Bsm[kb + 3][c] = v.w;
    }

    const int rowg = tid >> 5;
    const int cg4  = (tid & 31) * 4;

    for (int t2 = 0; t2 < 2; t2++) {
        const int n0 = blockIdx.y * 128 + t2 * 64;
        if (n0 >= N_) break;

        // load U tile for this n-tile (sync also covers B on first iter)
        __syncthreads();
        #pragma unroll
        for (int t = 0; t < 2; t++) {
            int idx = tid + t * 256;
            int k = idx >> 4;
            int nq = (idx & 15) * 4;
            float4 s = *(const float4*)&g_Ut[0][b][k][n0 + nq];
            float4 p = *(const float4*)&g_Ut[1][b][k][n0 + nq];
            s.x += p.x; s.y += p.y; s.z += p.z; s.w += p.w;
            *(float4*)&Usm[k][nq] = s;
        }
        __syncthreads();

        float2 acc[8][4];
        #pragma unroll
        for (int i = 0; i < 8; i++)
            #pragma unroll
            for (int j = 0; j < 4; j++) acc[i][j] = make_float2(0.f, 0.f);

        #pragma unroll
        for (int k = 0; k < 32; k++) {
            float4 u0 = *(const float4*)&Usm[k][rowg * 4];
            float4 u1 = *(const float4*)&Usm[k][32 + rowg * 4];
            float4 b0 = *(const float4*)&Bsm[k][cg4];
            float4 b1 = *(const float4*)&Bsm[k][128 + cg4];
            float2 bp0 = make_float2(b0.x, b0.y);
            float2 bp1 = make_float2(b0.z, b0.w);
            float2 bp2 = make_float2(b1.x, b1.y);
            float2 bp3 = make_float2(b1.z, b1.w);
            float us[8] = {u0.x, u0.y, u0.z, u0.w, u1.x, u1.y, u1.z, u1.w};
            #pragma unroll
            for (int i = 0; i < 8; i++) {
                float2 ud = make_float2(us[i], us[i]);
                ffma2_acc(acc[i][0], ud, bp0);
                ffma2_acc(acc[i][1], ud, bp1);
                ffma2_acc(acc[i][2], ud, bp2);
                ffma2_acc(acc[i][3], ud, bp3);
            }
        }

        #pragma unroll
        for (int i = 0; i < 8; i++) {
            int n = n0 + ((i < 4) ? (rowg * 4 + i) : (32 + rowg * 4 + i - 4));
            if (n < N_) {
                float* orow = &out[((size_t)b * N_ + n) * C3_ + c0];
                *(float4*)&orow[cg4] =
                    make_float4(acc[i][0].x, acc[i][0].y, acc[i][1].x, acc[i][1].y);
                *(float4*)&orow[128 + cg4] =
                    make_float4(acc[i][2].x, acc[i][2].y, acc[i][3].x, acc[i][3].y);
            }
        }
    }
}

// ---------------------------------------------------------------------------
extern "C" void kernel_launch(void* const* d_in, const int* in_sizes, int n_in,
                              void* d_out, int out_size) {
    const float* tokens  = (const float*)d_in[0];
    const float* gate_w  = (const float*)d_in[1];
    const float* lora_a  = (const float*)d_in[2];
    const float* lora_b  = (const float*)d_in[3];
    const float* scaling = (const float*)d_in[4];
    float* out = (float*)d_out;

    prep_kernel<<<256, 256>>>(tokens);
    logits_topk<<<B_, 256>>>(gate_w, scaling, out);
    u_kernel<<<dim3(19, B_, KQ), 256>>>(tokens, lora_a, out);
    out_kernel<<<dim3(12, 5, B_), 256>>>(lora_b, out);
}

// round 14
// speedup vs baseline: 3.2819x; 1.0334x over previous
#include <cuda_runtime.h>
#include <math.h>

#define B_  16
#define N_  577
#define D_  1024
#define E_  8
#define R_  16
#define C3_ 3072
#define NPAD 640
#define NCH 16
#define KQ  2

#define WU_SIZE   (B_ * N_ * C3_)
#define RL_OFF    (WU_SIZE)
#define TI_OFF    (RL_OFF + B_ * E_)
#define EW_OFF    (TI_OFF + B_ * 2)
#define IMP_OFF   (EW_OFF + B_ * E_)
#define LOAD_OFF  (IMP_OFF + E_)

__device__ float g_part[NCH][B_][D_];
__device__ int   g_sel[B_][2];
__device__ float g_coef[B_][2];
__device__ float g_w[B_][2];
__device__ float g_Ut[KQ][B_][32][NPAD];  // k-split partials of U^T

__device__ __forceinline__ void ffma2_acc(float2& d, float2 a, float2 b) {
    asm("fma.rn.f32x2 %0, %1, %2, %0;"
        : "+l"(reinterpret_cast<unsigned long long&>(d))
        : "l"(reinterpret_cast<unsigned long long&>(a)),
          "l"(reinterpret_cast<unsigned long long&>(b)));
}

// ---- Kernel 1: pooled partial sums over 16 n-chunks (proven) ----
__global__ __launch_bounds__(256) void prep_kernel(const float* __restrict__ tokens) {
    int bx = blockIdx.x;
    int b = bx >> 4, ch = bx & 15;
    int tid = threadIdx.x;
    int n0 = ch * 37, n1 = min(N_, n0 + 37);

    float4 acc = make_float4(0.f, 0.f, 0.f, 0.f);
    const float* base = tokens + (size_t)b * N_ * D_;
    for (int n = n0; n < n1; n++) {
        float4 v = *(const float4*)&base[n * D_ + tid * 4];
        acc.x += v.x; acc.y += v.y; acc.z += v.z; acc.w += v.w;
    }
    *(float4*)&g_part[ch][b][tid * 4] = acc;
}

// ---- Kernel 2: per-batch logits + top-2 softmax + aux outputs (proven) ----
__global__ __launch_bounds__(256) void logits_topk(const float* __restrict__ gate_w,
                                                   const float* __restrict__ scaling,
                                                   float* __restrict__ out) {
    __shared__ float pooled_s[D_];
    __shared__ float logits_s[E_];
    __shared__ int   m_s[2];
    __shared__ float w_s[2];

    const int b = blockIdx.x;
    const int tid = threadIdx.x;
    const int wid = tid >> 5, lane = tid & 31;

    float4 a = make_float4(0.f, 0.f, 0.f, 0.f);
    #pragma unroll
    for (int ch = 0; ch < NCH; ch++) {
        float4 v = *(const float4*)&g_part[ch][b][tid * 4];
        a.x += v.x; a.y += v.y; a.z += v.z; a.w += v.w;
    }
    *(float4*)&pooled_s[tid * 4] = a;
    __syncthreads();

    {
        float acc = 0.f;
        for (int d = lane; d < D_; d += 32)
            acc += pooled_s[d] * gate_w[d * E_ + wid];
        #pragma unroll
        for (int o = 16; o; o >>= 1) acc += __shfl_down_sync(0xffffffffu, acc, o);
        if (lane == 0) {
            float lg = acc * (1.0f / (float)N_);
            logits_s[wid] = lg;
            out[RL_OFF + b * E_ + wid] = lg;
        }
    }
    __syncthreads();

    if (tid == 0) {
        float v[E_];
        #pragma unroll
        for (int e = 0; e < E_; e++) v[e] = logits_s[e];
        int m1 = 0;
        #pragma unroll
        for (int e = 1; e < E_; e++) if (v[e] > v[m1]) m1 = e;
        int m2 = (m1 == 0) ? 1 : 0;
        #pragma unroll
        for (int e = 0; e < E_; e++) if (e != m1 && v[e] > v[m2]) m2 = e;

        float e2 = expf(v[m2] - v[m1]);
        float inv = 1.0f / (1.0f + e2);
        float w1 = inv, w2 = e2 * inv;

        m_s[0] = m1; m_s[1] = m2;
        w_s[0] = w1; w_s[1] = w2;
        g_sel[b][0] = m1; g_sel[b][1] = m2;
        g_w[b][0] = w1; g_w[b][1] = w2;
        g_coef[b][0] = w1 * scaling[m1];
        g_coef[b][1] = w2 * scaling[m2];
        out[TI_OFF + b * 2 + 0] = (float)m1;
        out[TI_OFF + b * 2 + 1] = (float)m2;
    }
    __syncthreads();

    if (tid < E_) {
        float w = (tid == m_s[0]) ? w_s[0] : ((tid == m_s[1]) ? w_s[1] : 0.f);
        out[EW_OFF + b * E_ + tid] = w;
    }
}

// ---- Kernel 3: U partials, smem-transposed coalesced stores (proven) ----
#define UKC 64
__global__ __launch_bounds__(256) void u_kernel(const float* __restrict__ tokens,
                                                const float* __restrict__ lora_a,
                                                float* __restrict__ out) {
    __shared__ union {
        struct { float T[32][UKC + 4]; float A[32][UKC + 4]; } p;
        float red[4][32][36];
    } sm;

    const int n0 = blockIdx.x * 32;
    const int b  = blockIdx.y;
    const int kq = blockIdx.z;
    const int tid = threadIdx.x;

    if (blockIdx.x == 0 && blockIdx.y == 0 && blockIdx.z == 0 && tid < E_) {
        float imp = 0.f; int ld = 0;
        for (int bb = 0; bb < B_; bb++) {
            if (g_sel[bb][0] == tid) { imp += g_w[bb][0]; ld++; }
            if (g_sel[bb][1] == tid) { imp += g_w[bb][1]; ld++; }
        }
        out[IMP_OFF + tid] = imp;
        out[LOAD_OFF + tid] = (float)ld;
    }

    const int s0 = g_sel[b][0], s1 = g_sel[b][1];
    const float c0f = g_coef[b][0], c1f = g_coef[b][1];

    const int kg   = tid >> 5;
    const int rowg = (tid >> 3) & 3;
    const int colg = tid & 7;

    float2 acc[8][4];
    #pragma unroll
    for (int i = 0; i < 8; i++)
        #pragma unroll
        for (int j = 0; j < 4; j++) acc[i][j] = make_float2(0.f, 0.f);

    const int kend = kq * 512 + 512;
    for (int k0 = kq * 512; k0 < kend; k0 += UKC) {
        #pragma unroll
        for (int t = 0; t < 2; t++) {
            int idx = tid + t * 256;
            int r = idx >> 4;
            int q = (idx & 15) * 4;
            float4 tv = make_float4(0.f, 0.f, 0.f, 0.f);
            if (n0 + r < N_)
                tv = *(const float4*)&tokens[((size_t)b * N_ + n0 + r) * D_ + k0 + q];
            *(float4*)&sm.p.T[r][q] = tv;

            int e = (r < 16) ? s0 : s1;
            float cf = (r < 16) ? c0f : c1f;
            float4 av = *(const float4*)&lora_a[((size_t)e * R_ + (r & 15)) * D_ + k0 + q];
            av.x *= cf; av.y *= cf; av.z *= cf; av.w *= cf;
            *(float4*)&sm.p.A[r][q] = av;
        }
        __syncthreads();

        const int kb = kg * 8;
        #pragma unroll
        for (int ks = 0; ks < 8; ks += 4) {
            float4 avv[4];
            #pragma unroll
            for (int j = 0; j < 4; j++)
                avv[j] = *(const float4*)&sm.p.A[colg + 8 * j][kb + ks];
            #pragma unroll
            for (int i = 0; i < 8; i++) {
                float4 tv = *(const float4*)&sm.p.T[rowg + 4 * i][kb + ks];
                #pragma unroll
                for (int j = 0; j < 4; j++) {
                    ffma2_acc(acc[i][j], make_float2(tv.x, tv.y),
                                         make_float2(avv[j].x, avv[j].y));
                    ffma2_acc(acc[i][j], make_float2(tv.z, tv.w),
                                         make_float2(avv[j].z, avv[j].w));
                }
            }
        }
        __syncthreads();
    }

    float v[8][4];
    #pragma unroll
    for (int i = 0; i < 8; i++)
        #pragma unroll
        for (int j = 0; j < 4; j++) v[i][j] = acc[i][j].x + acc[i][j].y;

    for (int off = 4; off; off >>= 1) {
        if (kg >= off && kg < 2 * off) {
            #pragma unroll
            for (int i = 0; i < 8; i++)
                #pragma unroll
                for (int j = 0; j < 4; j++)
                    sm.red[kg - off][colg + 8 * j][rowg + 4 * i] = v[i][j];
        }
        __syncthreads();
        if (kg < off) {
            #pragma unroll
            for (int i = 0; i < 8; i++)
                #pragma unroll
                for (int j = 0; j < 4; j++)
                    v[i][j] += sm.red[kg][colg + 8 * j][rowg + 4 * i];
        }
        __syncthreads();
    }

    if (kg == 0) {
        #pragma unroll
        for (int i = 0; i < 8; i++)
            #pragma unroll
            for (int j = 0; j < 4; j++)
                sm.red[0][colg + 8 * j][rowg + 4 * i] = v[i][j];
    }
    __syncthreads();
    {
        int j  = tid >> 3;
        int nq = (tid & 7) * 4;
        *(float4*)&g_Ut[kq][b][j][n0 + nq] = *(const float4*)&sm.red[0][j][nq];
    }
}

// ===========================================================================
// Kernel 4 (NEW): out GEMM on legacy tensor cores: mma.sync m16n8k8 tf32
// with hi/lo split (3 terms). Block 64m x 128n, 8 warps (4m x 2n).
// ===========================================================================
__device__ __forceinline__ void tf32_split(float x, unsigned& h, unsigned& l) {
    unsigned hb = __float_as_uint(x) & 0xFFFFE000u;
    h = hb;
    l = __float_as_uint(x - __uint_as_float(hb));
}

__device__ __forceinline__ void mma_tf32(float* c, const unsigned* a, const unsigned* b) {
    asm volatile(
        "mma.sync.aligned.m16n8k8.row.col.f32.tf32.tf32.f32 "
        "{%0,%1,%2,%3}, {%4,%5,%6,%7}, {%8,%9}, {%0,%1,%2,%3};"
        : "+f"(c[0]), "+f"(c[1]), "+f"(c[2]), "+f"(c[3])
        : "r"(a[0]), "r"(a[1]), "r"(a[2]), "r"(a[3]), "r"(b[0]), "r"(b[1]));
}

__global__ __launch_bounds__(256) void out_mma(const float* __restrict__ lora_b,
                                               float* __restrict__ out) {
    __shared__ float Usm[32][72];    // [k][m], stride 72 -> bank-conflict-free frags
    __shared__ float Bsm[32][136];   // [k][n], stride 136 -> conflict-free frags

    const int cbase = blockIdx.x * 128;
    const int m0    = blockIdx.y * 64;
    const int b     = blockIdx.z;
    const int tid = threadIdx.x;
    const int wid = tid >> 5;
    const int lane = tid & 31;
    const int gid = lane >> 2;       // 0..7
    const int tig = lane & 3;        // 0..3
    const int s0 = g_sel[b][0], s1 = g_sel[b][1];

    // U tile: [32k][64m] from k-split partials (coalesced float4 rows)
    #pragma unroll
    for (int t = 0; t < 2; t++) {
        int idx = tid + t * 256;
        int k = idx >> 4;
        int mq = (idx & 15) * 4;
        float4 s = *(const float4*)&g_Ut[0][b][k][m0 + mq];
        float4 p = *(const float4*)&g_Ut[1][b][k][m0 + mq];
        s.x += p.x; s.y += p.y; s.z += p.z; s.w += p.w;
        *(float4*)&Usm[k][mq] = s;
    }
    // B tile: [32k][128n]; k<16 -> expert s0 rank k, k>=16 -> s1 rank k-16
    #pragma unroll
    for (int t = 0; t < 4; t++) {
        int idx = tid + t * 256;     // 0..1023
        int c  = idx & 127;
        int er = idx >> 7;           // 0..7
        int e  = (er >= 4) ? s1 : s0;
        float4 v = *(const float4*)&lora_b[((size_t)e * C3_ + cbase + c) * R_ + (er & 3) * 4];
        int kb = er * 4;
        Bsm[kb + 0][c] = v.x;
        Bsm[kb + 1][c] = v.y;
        Bsm[kb + 2][c] = v.z;
        Bsm[kb + 3][c] = v.w;
    }
    __syncthreads();

    const int mw = (wid & 3) * 16;   // warp m-offset
    const int nw = (wid >> 2) * 64;  // warp n-offset

    float C[8][4];
    #pragma unroll
    for (int ns = 0; ns < 8; ns++)
        #pragma unroll
        for (int j = 0; j < 4; j++) C[ns][j] = 0.f;

    #pragma unroll
    for (int ks = 0; ks < 4; ks++) {
        const int kb = ks * 8;
        // A fragments (row = m, col = k): a0(gid,tig) a1(gid+8,tig) a2(gid,tig+4) a3(gid+8,tig+4)
        float af0 = Usm[kb + tig][mw + gid];
        float af1 = Usm[kb + tig][mw + gid + 8];
        float af2 = Usm[kb + tig + 4][mw + gid];
        float af3 = Usm[kb + tig + 4][mw + gid + 8];
        unsigned ah[4], al[4];
        tf32_split(af0, ah[0], al[0]);
        tf32_split(af1, ah[1], al[1]);
        tf32_split(af2, ah[2], al[2]);
        tf32_split(af3, ah[3], al[3]);

        #pragma unroll
        for (int ns = 0; ns < 8; ns++) {
            // B fragments (col-major k x n): b0(tig, gid), b1(tig+4, gid)
            float bf0 = Bsm[kb + tig][nw + ns * 8 + gid];
            float bf1 = Bsm[kb + tig + 4][nw + ns * 8 + gid];
            unsigned bh[2], bl[2];
            tf32_split(bf0, bh[0], bl[0]);
            tf32_split(bf1, bh[1], bl[1]);
            mma_tf32(C[ns], ah, bh);
            mma_tf32(C[ns], al, bh);
            mma_tf32(C[ns], ah, bl);
        }
    }

    // C fragments: c0(gid, 2tig) c1(gid, 2tig+1) c2(gid+8, 2tig) c3(gid+8, 2tig+1)
    const int r0 = m0 + mw + gid;
    const int r1 = r0 + 8;
    #pragma unroll
    for (int ns = 0; ns < 8; ns++) {
        int col = cbase + nw + ns * 8 + 2 * tig;
        if (r0 < N_)
            *(float2*)&out[((size_t)b * N_ + r0) * C3_ + col] =
                make_float2(C[ns][0], C[ns][1]);
        if (r1 < N_)
            *(float2*)&out[((size_t)b * N_ + r1) * C3_ + col] =
                make_float2(C[ns][2], C[ns][3]);
    }
}

// ---------------------------------------------------------------------------
extern "C" void kernel_launch(void* const* d_in, const int* in_sizes, int n_in,
                              void* d_out, int out_size) {
    const float* tokens  = (const float*)d_in[0];
    const float* gate_w  = (const float*)d_in[1];
    const float* lora_a  = (const float*)d_in[2];
    const float* lora_b  = (const float*)d_in[3];
    const float* scaling = (const float*)d_in[4];
    float* out = (float*)d_out;

    prep_kernel<<<256, 256>>>(tokens);
    logits_topk<<<B_, 256>>>(gate_w, scaling, out);
    u_kernel<<<dim3(19, B_, KQ), 256>>>(tokens, lora_a, out);
    out_mma<<<dim3(24, 10, B_), 256>>>(lora_b, out);
}

// round 16
// speedup vs baseline: 3.4154x; 1.0407x over previous
#include <cuda_runtime.h>
#include <math.h>

#define B_  16
#define N_  577
#define D_  1024
#define E_  8
#define R_  16
#define C3_ 3072
#define NPAD 640
#define NCH 16
#define KQ  2

#define WU_SIZE   (B_ * N_ * C3_)
#define RL_OFF    (WU_SIZE)
#define TI_OFF    (RL_OFF + B_ * E_)
#define EW_OFF    (TI_OFF + B_ * 2)
#define IMP_OFF   (EW_OFF + B_ * E_)
#define LOAD_OFF  (IMP_OFF + E_)

__device__ float g_part[NCH][B_][D_];
__device__ int   g_sel[B_][2];
__device__ float g_coef[B_][2];
__device__ float g_w[B_][2];
__device__ float g_Ut[KQ][B_][32][NPAD];  // k-split partials of U^T

__device__ __forceinline__ void ffma2_acc(float2& d, float2 a, float2 b) {
    asm("fma.rn.f32x2 %0, %1, %2, %0;"
        : "+l"(reinterpret_cast<unsigned long long&>(d))
        : "l"(reinterpret_cast<unsigned long long&>(a)),
          "l"(reinterpret_cast<unsigned long long&>(b)));
}

// ---- Kernel 1: pooled partial sums over 16 n-chunks (proven) ----
__global__ __launch_bounds__(256) void prep_kernel(const float* __restrict__ tokens) {
    int bx = blockIdx.x;
    int b = bx >> 4, ch = bx & 15;
    int tid = threadIdx.x;
    int n0 = ch * 37, n1 = min(N_, n0 + 37);

    float4 acc = make_float4(0.f, 0.f, 0.f, 0.f);
    const float* base = tokens + (size_t)b * N_ * D_;
    for (int n = n0; n < n1; n++) {
        float4 v = *(const float4*)&base[n * D_ + tid * 4];
        acc.x += v.x; acc.y += v.y; acc.z += v.z; acc.w += v.w;
    }
    *(float4*)&g_part[ch][b][tid * 4] = acc;
}

// ---- Kernel 2: per-batch logits + top-2 softmax + aux outputs (proven) ----
__global__ __launch_bounds__(256) void logits_topk(const float* __restrict__ gate_w,
                                                   const float* __restrict__ scaling,
                                                   float* __restrict__ out) {
    __shared__ float pooled_s[D_];
    __shared__ float logits_s[E_];
    __shared__ int   m_s[2];
    __shared__ float w_s[2];

    const int b = blockIdx.x;
    const int tid = threadIdx.x;
    const int wid = tid >> 5, lane = tid & 31;

    float4 a = make_float4(0.f, 0.f, 0.f, 0.f);
    #pragma unroll
    for (int ch = 0; ch < NCH; ch++) {
        float4 v = *(const float4*)&g_part[ch][b][tid * 4];
        a.x += v.x; a.y += v.y; a.z += v.z; a.w += v.w;
    }
    *(float4*)&pooled_s[tid * 4] = a;
    __syncthreads();

    {
        float acc = 0.f;
        for (int d = lane; d < D_; d += 32)
            acc += pooled_s[d] * gate_w[d * E_ + wid];
        #pragma unroll
        for (int o = 16; o; o >>= 1) acc += __shfl_down_sync(0xffffffffu, acc, o);
        if (lane == 0) {
            float lg = acc * (1.0f / (float)N_);
            logits_s[wid] = lg;
            out[RL_OFF + b * E_ + wid] = lg;
        }
    }
    __syncthreads();

    if (tid == 0) {
        float v[E_];
        #pragma unroll
        for (int e = 0; e < E_; e++) v[e] = logits_s[e];
        int m1 = 0;
        #pragma unroll
        for (int e = 1; e < E_; e++) if (v[e] > v[m1]) m1 = e;
        int m2 = (m1 == 0) ? 1 : 0;
        #pragma unroll
        for (int e = 0; e < E_; e++) if (e != m1 && v[e] > v[m2]) m2 = e;

        float e2 = expf(v[m2] - v[m1]);
        float inv = 1.0f / (1.0f + e2);
        float w1 = inv, w2 = e2 * inv;

        m_s[0] = m1; m_s[1] = m2;
        w_s[0] = w1; w_s[1] = w2;
        g_sel[b][0] = m1; g_sel[b][1] = m2;
        g_w[b][0] = w1; g_w[b][1] = w2;
        g_coef[b][0] = w1 * scaling[m1];
        g_coef[b][1] = w2 * scaling[m2];
        out[TI_OFF + b * 2 + 0] = (float)m1;
        out[TI_OFF + b * 2 + 1] = (float)m2;
    }
    __syncthreads();

    if (tid < E_) {
        float w = (tid == m_s[0]) ? w_s[0] : ((tid == m_s[1]) ? w_s[1] : 0.f);
        out[EW_OFF + b * E_ + tid] = w;
    }
}

// ---- Kernel 3: U partials, smem-transposed coalesced stores (proven) ----
#define UKC 64
__global__ __launch_bounds__(256) void u_kernel(const float* __restrict__ tokens,
                                                const float* __restrict__ lora_a,
                                                float* __restrict__ out) {
    __shared__ union {
        struct { float T[32][UKC + 4]; float A[32][UKC + 4]; } p;
        float red[4][32][36];
    } sm;

    const int n0 = blockIdx.x * 32;
    const int b  = blockIdx.y;
    const int kq = blockIdx.z;
    const int tid = threadIdx.x;

    if (blockIdx.x == 0 && blockIdx.y == 0 && blockIdx.z == 0 && tid < E_) {
        float imp = 0.f; int ld = 0;
        for (int bb = 0; bb < B_; bb++) {
            if (g_sel[bb][0] == tid) { imp += g_w[bb][0]; ld++; }
            if (g_sel[bb][1] == tid) { imp += g_w[bb][1]; ld++; }
        }
        out[IMP_OFF + tid] = imp;
        out[LOAD_OFF + tid] = (float)ld;
    }

    const int s0 = g_sel[b][0], s1 = g_sel[b][1];
    const float c0f = g_coef[b][0], c1f = g_coef[b][1];

    const int kg   = tid >> 5;
    const int rowg = (tid >> 3) & 3;
    const int colg = tid & 7;

    float2 acc[8][4];
    #pragma unroll
    for (int i = 0; i < 8; i++)
        #pragma unroll
        for (int j = 0; j < 4; j++) acc[i][j] = make_float2(0.f, 0.f);

    const int kend = kq * 512 + 512;
    for (int k0 = kq * 512; k0 < kend; k0 += UKC) {
        #pragma unroll
        for (int t = 0; t < 2; t++) {
            int idx = tid + t * 256;
            int r = idx >> 4;
            int q = (idx & 15) * 4;
            float4 tv = make_float4(0.f, 0.f, 0.f, 0.f);
            if (n0 + r < N_)
                tv = *(const float4*)&tokens[((size_t)b * N_ + n0 + r) * D_ + k0 + q];
            *(float4*)&sm.p.T[r][q] = tv;

            int e = (r < 16) ? s0 : s1;
            float cf = (r < 16) ? c0f : c1f;
            float4 av = *(const float4*)&lora_a[((size_t)e * R_ + (r & 15)) * D_ + k0 + q];
            av.x *= cf; av.y *= cf; av.z *= cf; av.w *= cf;
            *(float4*)&sm.p.A[r][q] = av;
        }
        __syncthreads();

        const int kb = kg * 8;
        #pragma unroll
        for (int ks = 0; ks < 8; ks += 4) {
            float4 avv[4];
            #pragma unroll
            for (int j = 0; j < 4; j++)
                avv[j] = *(const float4*)&sm.p.A[colg + 8 * j][kb + ks];
            #pragma unroll
            for (int i = 0; i < 8; i++) {
                float4 tv = *(const float4*)&sm.p.T[rowg + 4 * i][kb + ks];
                #pragma unroll
                for (int j = 0; j < 4; j++) {
                    ffma2_acc(acc[i][j], make_float2(tv.x, tv.y),
                                         make_float2(avv[j].x, avv[j].y));
                    ffma2_acc(acc[i][j], make_float2(tv.z, tv.w),
                                         make_float2(avv[j].z, avv[j].w));
                }
            }
        }
        __syncthreads();
    }

    float v[8][4];
    #pragma unroll
    for (int i = 0; i < 8; i++)
        #pragma unroll
        for (int j = 0; j < 4; j++) v[i][j] = acc[i][j].x + acc[i][j].y;

    for (int off = 4; off; off >>= 1) {
        if (kg >= off && kg < 2 * off) {
            #pragma unroll
            for (int i = 0; i < 8; i++)
                #pragma unroll
                for (int j = 0; j < 4; j++)
                    sm.red[kg - off][colg + 8 * j][rowg + 4 * i] = v[i][j];
        }
        __syncthreads();
        if (kg < off) {
            #pragma unroll
            for (int i = 0; i < 8; i++)
                #pragma unroll
                for (int j = 0; j < 4; j++)
                    v[i][j] += sm.red[kg][colg + 8 * j][rowg + 4 * i];
        }
        __syncthreads();
    }

    if (kg == 0) {
        #pragma unroll
        for (int i = 0; i < 8; i++)
            #pragma unroll
            for (int j = 0; j < 4; j++)
                sm.red[0][colg + 8 * j][rowg + 4 * i] = v[i][j];
    }
    __syncthreads();
    {
        int j  = tid >> 3;
        int nq = (tid & 7) * 4;
        *(float4*)&g_Ut[kq][b][j][n0 + nq] = *(const float4*)&sm.red[0][j][nq];
    }
}

// ===========================================================================
// Kernel 4: tf32 mma.sync, hi/lo 3-term. Block 128m x 128n, warp 32m x 64n.
// ===========================================================================
__device__ __forceinline__ void tf32_split(float x, unsigned& h, unsigned& l) {
    unsigned hb = __float_as_uint(x) & 0xFFFFE000u;
    h = hb;
    l = __float_as_uint(x - __uint_as_float(hb));
}

__device__ __forceinline__ void mma_tf32(float* c, const unsigned* a, const unsigned* b) {
    asm volatile(
        "mma.sync.aligned.m16n8k8.row.col.f32.tf32.tf32.f32 "
        "{%0,%1,%2,%3}, {%4,%5,%6,%7}, {%8,%9}, {%0,%1,%2,%3};"
        : "+f"(c[0]), "+f"(c[1]), "+f"(c[2]), "+f"(c[3])
        : "r"(a[0]), "r"(a[1]), "r"(a[2]), "r"(a[3]), "r"(b[0]), "r"(b[1]));
}

__global__ void out_mma(const float* __restrict__ lora_b,
                        float* __restrict__ out) {
    __shared__ float Usm[32][136];   // [k][m], stride 136 -> conflict-free frags
    __shared__ float Bsm[32][136];   // [k][n]

    const int cbase = blockIdx.x * 128;
    const int m0    = blockIdx.y * 128;
    const int b     = blockIdx.z;
    const int tid = threadIdx.x;
    const int wid = tid >> 5;
    const int lane = tid & 31;
    const int gid = lane >> 2;       // 0..7
    const int tig = lane & 3;        // 0..3
    const int s0 = g_sel[b][0], s1 = g_sel[b][1];

    // U tile: [32k][128m] (coalesced float4 rows; conflict-free stores)
    #pragma unroll
    for (int t = 0; t < 4; t++) {
        int idx = tid + t * 256;     // 0..1023
        int k = idx >> 5;
        int mq = (idx & 31) * 4;
        float4 s = *(const float4*)&g_Ut[0][b][k][m0 + mq];
        float4 p = *(const float4*)&g_Ut[1][b][k][m0 + mq];
        s.x += p.x; s.y += p.y; s.z += p.z; s.w += p.w;
        *(float4*)&Usm[k][mq] = s;
    }
    // B tile: [32k][128n]; k<16 -> expert s0, k>=16 -> s1 (conflict-free stores)
    #pragma unroll
    for (int t = 0; t < 4; t++) {
        int idx = tid + t * 256;     // 0..1023
        int o = idx >> 7;            // 0..7
        int c = idx & 127;
        int e = (o >= 4) ? s1 : s0;
        float4 v = *(const float4*)&lora_b[((size_t)e * C3_ + cbase + c) * R_ + (o & 3) * 4];
        int kb = ((o >= 4) ? 16 : 0) + (o & 3) * 4;
        Bsm[kb + 0][c] = v.x;
        Bsm[kb + 1][c] = v.y;
        Bsm[kb + 2][c] = v.z;
        Bsm[kb + 3][c] = v.w;
    }
    __syncthreads();

    const int mw = (wid & 3) * 32;   // warp m-offset (2 m16 tiles)
    const int nw = (wid >> 2) * 64;  // warp n-offset

    float C[2][8][4];
    #pragma unroll
    for (int mt = 0; mt < 2; mt++)
        #pragma unroll
        for (int ns = 0; ns < 8; ns++)
            #pragma unroll
            for (int j = 0; j < 4; j++) C[mt][ns][j] = 0.f;

    #pragma unroll
    for (int ks = 0; ks < 4; ks++) {
        const int kb = ks * 8;
        unsigned ah[2][4], al[2][4];
        #pragma unroll
        for (int mt = 0; mt < 2; mt++) {
            int mb = mw + mt * 16;
            tf32_split(Usm[kb + tig][mb + gid],         ah[mt][0], al[mt][0]);
            tf32_split(Usm[kb + tig][mb + gid + 8],     ah[mt][1], al[mt][1]);
            tf32_split(Usm[kb + tig + 4][mb + gid],     ah[mt][2], al[mt][2]);
            tf32_split(Usm[kb + tig + 4][mb + gid + 8], ah[mt][3], al[mt][3]);
        }
        #pragma unroll
        for (int ns = 0; ns < 8; ns++) {
            float bf0 = Bsm[kb + tig][nw + ns * 8 + gid];
            float bf1 = Bsm[kb + tig + 4][nw + ns * 8 + gid];
            unsigned bh[2], bl[2];
            tf32_split(bf0, bh[0], bl[0]);
            tf32_split(bf1, bh[1], bl[1]);
            #pragma unroll
            for (int mt = 0; mt < 2; mt++) {
                mma_tf32(C[mt][ns], ah[mt], bh);
                mma_tf32(C[mt][ns], al[mt], bh);
                mma_tf32(C[mt][ns], ah[mt], bl);
            }
        }
    }

    // C fragments: c0(gid, 2tig) c1(gid, 2tig+1) c2(gid+8, 2tig) c3(gid+8, 2tig+1)
    #pragma unroll
    for (int mt = 0; mt < 2; mt++) {
        const int r0 = m0 + mw + mt * 16 + gid;
        const int r1 = r0 + 8;
        #pragma unroll
        for (int ns = 0; ns < 8; ns++) {
            int col = cbase + nw + ns * 8 + 2 * tig;
            if (r0 < N_)
                *(float2*)&out[((size_t)b * N_ + r0) * C3_ + col] =
                    make_float2(C[mt][ns][0], C[mt][ns][1]);
            if (r1 < N_)
                *(float2*)&out[((size_t)b * N_ + r1) * C3_ + col] =
                    make_float2(C[mt][ns][2], C[mt][ns][3]);
        }
    }
}

// ---------------------------------------------------------------------------
extern "C" void kernel_launch(void* const* d_in, const int* in_sizes, int n_in,
                              void* d_out, int out_size) {
    const float* tokens  = (const float*)d_in[0];
    const float* gate_w  = (const float*)d_in[1];
    const float* lora_a  = (const float*)d_in[2];
    const float* lora_b  = (const float*)d_in[3];
    const float* scaling = (const float*)d_in[4];
    float* out = (float*)d_out;

    prep_kernel<<<256, 256>>>(tokens);
    logits_topk<<<B_, 256>>>(gate_w, scaling, out);
    u_kernel<<<dim3(19, B_, KQ), 256>>>(tokens, lora_a, out);
    out_mma<<<dim3(24, 5, B_), 256>>>(lora_b, out);
}

// round 17
// speedup vs baseline: 3.6057x; 1.0557x over previous
#include <cuda_runtime.h>
#include <cuda_bf16.h>
#include <math.h>

#define B_  16
#define N_  577
#define D_  1024
#define E_  8
#define R_  16
#define C3_ 3072
#define NPAD 640
#define NCH 16
#define KQ  2

#define WU_SIZE   (B_ * N_ * C3_)
#define RL_OFF    (WU_SIZE)
#define TI_OFF    (RL_OFF + B_ * E_)
#define EW_OFF    (TI_OFF + B_ * 2)
#define IMP_OFF   (EW_OFF + B_ * E_)
#define LOAD_OFF  (IMP_OFF + E_)

__device__ float g_part[NCH][B_][D_];
__device__ int   g_sel[B_][2];
__device__ float g_coef[B_][2];
__device__ float g_w[B_][2];
__device__ float g_Ut[KQ][B_][32][NPAD];  // k-split partials of U^T

__device__ __forceinline__ void ffma2_acc(float2& d, float2 a, float2 b) {
    asm("fma.rn.f32x2 %0, %1, %2, %0;"
        : "+l"(reinterpret_cast<unsigned long long&>(d))
        : "l"(reinterpret_cast<unsigned long long&>(a)),
          "l"(reinterpret_cast<unsigned long long&>(b)));
}

// ---- Kernel 1: pooled partial sums over 16 n-chunks (proven) ----
__global__ __launch_bounds__(256) void prep_kernel(const float* __restrict__ tokens) {
    int bx = blockIdx.x;
    int b = bx >> 4, ch = bx & 15;
    int tid = threadIdx.x;
    int n0 = ch * 37, n1 = min(N_, n0 + 37);

    float4 acc = make_float4(0.f, 0.f, 0.f, 0.f);
    const float* base = tokens + (size_t)b * N_ * D_;
    for (int n = n0; n < n1; n++) {
        float4 v = *(const float4*)&base[n * D_ + tid * 4];
        acc.x += v.x; acc.y += v.y; acc.z += v.z; acc.w += v.w;
    }
    *(float4*)&g_part[ch][b][tid * 4] = acc;
}

// ---- Kernel 2: per-batch logits + top-2 softmax + aux outputs (proven) ----
__global__ __launch_bounds__(256) void logits_topk(const float* __restrict__ gate_w,
                                                   const float* __restrict__ scaling,
                                                   float* __restrict__ out) {
    __shared__ float pooled_s[D_];
    __shared__ float logits_s[E_];
    __shared__ int   m_s[2];
    __shared__ float w_s[2];

    const int b = blockIdx.x;
    const int tid = threadIdx.x;
    const int wid = tid >> 5, lane = tid & 31;

    float4 a = make_float4(0.f, 0.f, 0.f, 0.f);
    #pragma unroll
    for (int ch = 0; ch < NCH; ch++) {
        float4 v = *(const float4*)&g_part[ch][b][tid * 4];
        a.x += v.x; a.y += v.y; a.z += v.z; a.w += v.w;
    }
    *(float4*)&pooled_s[tid * 4] = a;
    __syncthreads();

    {
        float acc = 0.f;
        for (int d = lane; d < D_; d += 32)
            acc += pooled_s[d] * gate_w[d * E_ + wid];
        #pragma unroll
        for (int o = 16; o; o >>= 1) acc += __shfl_down_sync(0xffffffffu, acc, o);
        if (lane == 0) {
            float lg = acc * (1.0f / (float)N_);
            logits_s[wid] = lg;
            out[RL_OFF + b * E_ + wid] = lg;
        }
    }
    __syncthreads();

    if (tid == 0) {
        float v[E_];
        #pragma unroll
        for (int e = 0; e < E_; e++) v[e] = logits_s[e];
        int m1 = 0;
        #pragma unroll
        for (int e = 1; e < E_; e++) if (v[e] > v[m1]) m1 = e;
        int m2 = (m1 == 0) ? 1 : 0;
        #pragma unroll
        for (int e = 0; e < E_; e++) if (e != m1 && v[e] > v[m2]) m2 = e;

        float e2 = expf(v[m2] - v[m1]);
        float inv = 1.0f / (1.0f + e2);
        float w1 = inv, w2 = e2 * inv;

        m_s[0] = m1; m_s[1] = m2;
        w_s[0] = w1; w_s[1] = w2;
        g_sel[b][0] = m1; g_sel[b][1] = m2;
        g_w[b][0] = w1; g_w[b][1] = w2;
        g_coef[b][0] = w1 * scaling[m1];
        g_coef[b][1] = w2 * scaling[m2];
        out[TI_OFF + b * 2 + 0] = (float)m1;
        out[TI_OFF + b * 2 + 1] = (float)m2;
    }
    __syncthreads();

    if (tid < E_) {
        float w = (tid == m_s[0]) ? w_s[0] : ((tid == m_s[1]) ? w_s[1] : 0.f);
        out[EW_OFF + b * E_ + tid] = w;
    }
}

// ---- Kernel 3: U partials, smem-transposed coalesced stores (proven) ----
#define UKC 64
__global__ __launch_bounds__(256) void u_kernel(const float* __restrict__ tokens,
                                                const float* __restrict__ lora_a,
                                                float* __restrict__ out) {
    __shared__ union {
        struct { float T[32][UKC + 4]; float A[32][UKC + 4]; } p;
        float red[4][32][36];
    } sm;

    const int n0 = blockIdx.x * 32;
    const int b  = blockIdx.y;
    const int kq = blockIdx.z;
    const int tid = threadIdx.x;

    if (blockIdx.x == 0 && blockIdx.y == 0 && blockIdx.z == 0 && tid < E_) {
        float imp = 0.f; int ld = 0;
        for (int bb = 0; bb < B_; bb++) {
            if (g_sel[bb][0] == tid) { imp += g_w[bb][0]; ld++; }
            if (g_sel[bb][1] == tid) { imp += g_w[bb][1]; ld++; }
        }
        out[IMP_OFF + tid] = imp;
        out[LOAD_OFF + tid] = (float)ld;
    }

    const int s0 = g_sel[b][0], s1 = g_sel[b][1];
    const float c0f = g_coef[b][0], c1f = g_coef[b][1];

    const int kg   = tid >> 5;
    const int rowg = (tid >> 3) & 3;
    const int colg = tid & 7;

    float2 acc[8][4];
    #pragma unroll
    for (int i = 0; i < 8; i++)
        #pragma unroll
        for (int j = 0; j < 4; j++) acc[i][j] = make_float2(0.f, 0.f);

    const int kend = kq * 512 + 512;
    for (int k0 = kq * 512; k0 < kend; k0 += UKC) {
        #pragma unroll
        for (int t = 0; t < 2; t++) {
            int idx = tid + t * 256;
            int r = idx >> 4;
            int q = (idx & 15) * 4;
            float4 tv = make_float4(0.f, 0.f, 0.f, 0.f);
            if (n0 + r < N_)
                tv = *(const float4*)&tokens[((size_t)b * N_ + n0 + r) * D_ + k0 + q];
            *(float4*)&sm.p.T[r][q] = tv;

            int e = (r < 16) ? s0 : s1;
            float cf = (r < 16) ? c0f : c1f;
            float4 av = *(const float4*)&lora_a[((size_t)e * R_ + (r & 15)) * D_ + k0 + q];
            av.x *= cf; av.y *= cf; av.z *= cf; av.w *= cf;
            *(float4*)&sm.p.A[r][q] = av;
        }
        __syncthreads();

        const int kb = kg * 8;
        #pragma unroll
        for (int ks = 0; ks < 8; ks += 4) {
            float4 avv[4];
            #pragma unroll
            for (int j = 0; j < 4; j++)
                avv[j] = *(const float4*)&sm.p.A[colg + 8 * j][kb + ks];
            #pragma unroll
            for (int i = 0; i < 8; i++) {
                float4 tv = *(const float4*)&sm.p.T[rowg + 4 * i][kb + ks];
                #pragma unroll
                for (int j = 0; j < 4; j++) {
                    ffma2_acc(acc[i][j], make_float2(tv.x, tv.y),
                                         make_float2(avv[j].x, avv[j].y));
                    ffma2_acc(acc[i][j], make_float2(tv.z, tv.w),
                                         make_float2(avv[j].z, avv[j].w));
                }
            }
        }
        __syncthreads();
    }

    float v[8][4];
    #pragma unroll
    for (int i = 0; i < 8; i++)
        #pragma unroll
        for (int j = 0; j < 4; j++) v[i][j] = acc[i][j].x + acc[i][j].y;

    for (int off = 4; off; off >>= 1) {
        if (kg >= off && kg < 2 * off) {
            #pragma unroll
            for (int i = 0; i < 8; i++)
                #pragma unroll
                for (int j = 0; j < 4; j++)
                    sm.red[kg - off][colg + 8 * j][rowg + 4 * i] = v[i][j];
        }
        __syncthreads();
        if (kg < off) {
            #pragma unroll
            for (int i = 0; i < 8; i++)
                #pragma unroll
                for (int j = 0; j < 4; j++)
                    v[i][j] += sm.red[kg][colg + 8 * j][rowg + 4 * i];
        }
        __syncthreads();
    }

    if (kg == 0) {
        #pragma unroll
        for (int i = 0; i < 8; i++)
            #pragma unroll
            for (int j = 0; j < 4; j++)
                sm.red[0][colg + 8 * j][rowg + 4 * i] = v[i][j];
    }
    __syncthreads();
    {
        int j  = tid >> 3;
        int nq = (tid & 7) * 4;
        *(float4*)&g_Ut[kq][b][j][n0 + nq] = *(const float4*)&sm.red[0][j][nq];
    }
}

// ===========================================================================
// Kernel 4: bf16 m16n8k16 mma.sync, hi/lo 3-term, planes pre-split in smem.
// Block 128m x 128n, warp 32m x 64n.
// ===========================================================================
__device__ __forceinline__ unsigned pack2(float lo, float hi) {
    __nv_bfloat162 p = __halves2bfloat162(__float2bfloat16_rn(lo),
                                          __float2bfloat16_rn(hi));
    return *reinterpret_cast<unsigned*>(&p);
}
__device__ __forceinline__ void split2(float f0, float f1, unsigned& hw, unsigned& lw) {
    __nv_bfloat16 h0 = __float2bfloat16_rn(f0);
    __nv_bfloat16 h1 = __float2bfloat16_rn(f1);
    __nv_bfloat162 hp = __halves2bfloat162(h0, h1);
    hw = *reinterpret_cast<unsigned*>(&hp);
    lw = pack2(f0 - __bfloat162float(h0), f1 - __bfloat162float(h1));
}

__device__ __forceinline__ void mma_bf16(float* c, const unsigned* a, const unsigned* b) {
    asm volatile(
        "mma.sync.aligned.m16n8k16.row.col.f32.bf16.bf16.f32 "
        "{%0,%1,%2,%3}, {%4,%5,%6,%7}, {%8,%9}, {%0,%1,%2,%3};"
        : "+f"(c[0]), "+f"(c[1]), "+f"(c[2]), "+f"(c[3])
        : "r"(a[0]), "r"(a[1]), "r"(a[2]), "r"(a[3]), "r"(b[0]), "r"(b[1]));
}

__global__ void out_mma(const float* __restrict__ lora_b,
                        float* __restrict__ out) {
    // bf16x2 planes, packed along k (word j = k 2j lo, 2j+1 hi); stride 136
    __shared__ unsigned Uh[16][136], Ul[16][136];
    __shared__ unsigned Bh[16][136], Bl[16][136];

    const int cbase = blockIdx.x * 128;
    const int m0    = blockIdx.y * 128;
    const int b     = blockIdx.z;
    const int tid = threadIdx.x;
    const int wid = tid >> 5;
    const int lane = tid & 31;
    const int gid = lane >> 2;       // 0..7
    const int tig = lane & 3;        // 0..3
    const int s0 = g_sel[b][0], s1 = g_sel[b][1];

    // U planes: word row j covers k=2j,2j+1; 4 m per thread-iter (uint4 stores)
    #pragma unroll
    for (int t = 0; t < 2; t++) {
        int idx = tid + t * 256;     // 0..511
        int j  = idx >> 5;           // 0..15
        int mq = (idx & 31) * 4;
        float4 e0 = *(const float4*)&g_Ut[0][b][2 * j][m0 + mq];
        float4 p0 = *(const float4*)&g_Ut[1][b][2 * j][m0 + mq];
        float4 e1 = *(const float4*)&g_Ut[0][b][2 * j + 1][m0 + mq];
        float4 p1 = *(const float4*)&g_Ut[1][b][2 * j + 1][m0 + mq];
        e0.x += p0.x; e0.y += p0.y; e0.z += p0.z; e0.w += p0.w;
        e1.x += p1.x; e1.y += p1.y; e1.z += p1.z; e1.w += p1.w;
        unsigned hw[4], lw[4];
        split2(e0.x, e1.x, hw[0], lw[0]);
        split2(e0.y, e1.y, hw[1], lw[1]);
        split2(e0.z, e1.z, hw[2], lw[2]);
        split2(e0.w, e1.w, hw[3], lw[3]);
        *(uint4*)&Uh[j][mq] = make_uint4(hw[0], hw[1], hw[2], hw[3]);
        *(uint4*)&Ul[j][mq] = make_uint4(lw[0], lw[1], lw[2], lw[3]);
    }
    // B planes: abs k = o*4..o*4+3 -> word rows 2o, 2o+1
    #pragma unroll
    for (int t = 0; t < 4; t++) {
        int idx = tid + t * 256;     // 0..1023
        int o = idx >> 7;            // 0..7
        int c = idx & 127;
        int e = (o >= 4) ? s1 : s0;
        float4 v = *(const float4*)&lora_b[((size_t)e * C3_ + cbase + c) * R_ + (o & 3) * 4];
        unsigned hw0, lw0, hw1, lw1;
        split2(v.x, v.y, hw0, lw0);
        split2(v.z, v.w, hw1, lw1);
        Bh[2 * o][c] = hw0;  Bl[2 * o][c] = lw0;
        Bh[2 * o + 1][c] = hw1;  Bl[2 * o + 1][c] = lw1;
    }
    __syncthreads();

    const int mw = (wid & 3) * 32;   // warp m-offset (2 m16 tiles)
    const int nw = (wid >> 2) * 64;  // warp n-offset

    float C[2][8][4];
    #pragma unroll
    for (int mt = 0; mt < 2; mt++)
        #pragma unroll
        for (int ns = 0; ns < 8; ns++)
            #pragma unroll
            for (int j = 0; j < 4; j++) C[mt][ns][j] = 0.f;

    #pragma unroll
    for (int ks = 0; ks < 2; ks++) {
        const int r0 = ks * 8 + tig;
        const int r1 = r0 + 4;
        unsigned ah[2][4], al[2][4];
        #pragma unroll
        for (int mt = 0; mt < 2; mt++) {
            int mb = mw + mt * 16;
            ah[mt][0] = Uh[r0][mb + gid];
            ah[mt][1] = Uh[r0][mb + gid + 8];
            ah[mt][2] = Uh[r1][mb + gid];
            ah[mt][3] = Uh[r1][mb + gid + 8];
            al[mt][0] = Ul[r0][mb + gid];
            al[mt][1] = Ul[r0][mb + gid + 8];
            al[mt][2] = Ul[r1][mb + gid];
            al[mt][3] = Ul[r1][mb + gid + 8];
        }
        #pragma unroll
        for (int ns = 0; ns < 8; ns++) {
            int nc = nw + ns * 8 + gid;
            unsigned bh[2] = { Bh[r0][nc], Bh[r1][nc] };
            unsigned bl[2] = { Bl[r0][nc], Bl[r1][nc] };
            #pragma unroll
            for (int mt = 0; mt < 2; mt++) {
                mma_bf16(C[mt][ns], ah[mt], bh);
                mma_bf16(C[mt][ns], al[mt], bh);
                mma_bf16(C[mt][ns], ah[mt], bl);
            }
        }
    }

    // C fragments: c0(gid, 2tig) c1(gid, 2tig+1) c2(gid+8, 2tig) c3(gid+8, 2tig+1)
    #pragma unroll
    for (int mt = 0; mt < 2; mt++) {
        const int r0 = m0 + mw + mt * 16 + gid;
        const int r1 = r0 + 8;
        #pragma unroll
        for (int ns = 0; ns < 8; ns++) {
            int col = cbase + nw + ns * 8 + 2 * tig;
            if (r0 < N_)
                *(float2*)&out[((size_t)b * N_ + r0) * C3_ + col] =
                    make_float2(C[mt][ns][0], C[mt][ns][1]);
            if (r1 < N_)
                *(float2*)&out[((size_t)b * N_ + r1) * C3_ + col] =
                    make_float2(C[mt][ns][2], C[mt][ns][3]);
        }
    }
}

// ---------------------------------------------------------------------------
extern "C" void kernel_launch(void* const* d_in, const int* in_sizes, int n_in,
                              void* d_out, int out_size) {
    const float* tokens  = (const float*)d_in[0];
    const float* gate_w  = (const float*)d_in[1];
    const float* lora_a  = (const float*)d_in[2];
    const float* lora_b  = (const float*)d_in[3];
    const float* scaling = (const float*)d_in[4];
    float* out = (float*)d_out;

    prep_kernel<<<256, 256>>>(tokens);
    logits_topk<<<B_, 256>>>(gate_w, scaling, out);
    u_kernel<<<dim3(19, B_, KQ), 256>>>(tokens, lora_a, out);
    out_mma<<<dim3(24, 5, B_), 256>>>(lora_b, out);
}